// round 14
// baseline (speedup 1.0000x reference)
#include <cuda_runtime.h>
#include <cuda_fp16.h>
#include <cstdint>

// Problem constants
#define BATCH 32
#define NTOK  1024
#define FDIM  512
#define GRP   16
#define SEQ   64
#define DDIM  256
#define WIN   32
#define OCH   512
#define TOUT  993          // NTOK - WIN + 1
#define KTOT  (WIN * DDIM) // 8192
#define NEG_SLOPE 0.2f

// Scratch (device globals; no allocs allowed)
__device__ __half g_mid[BATCH * NTOK * DDIM];         // 16 MB, fp16 mid
__device__ __half g_cwT[OCH * KTOT];                  // 8 MB, conv_w transposed [O][K], fp16
__device__ __half g_xh [BATCH * NTOK * FDIM];         // 32 MB, x in fp16
__device__ __half g_wT [GRP * DDIM * FDIM];           // 4 MB, W transposed [g][d][f], fp16

__device__ __forceinline__ void cp16(unsigned smem, const void* g, int sz) {
    asm volatile("cp.async.ca.shared.global [%0], [%1], 16, %2;\n"
                 :: "r"(smem), "l"(g), "r"(sz));
}

__device__ __forceinline__ void ldsm4(unsigned* r, unsigned addr) {
    asm volatile("ldmatrix.sync.aligned.m8n8.x4.shared.b16 {%0,%1,%2,%3}, [%4];"
                 : "=r"(r[0]), "=r"(r[1]), "=r"(r[2]), "=r"(r[3]) : "r"(addr));
}

__device__ __forceinline__ void mma_f16(float* c, const unsigned* a, const unsigned* b) {
    asm volatile(
        "mma.sync.aligned.m16n8k16.row.col.f32.f16.f16.f32 "
        "{%0,%1,%2,%3}, {%4,%5,%6,%7}, {%8,%9}, {%0,%1,%2,%3};\n"
        : "+f"(c[0]), "+f"(c[1]), "+f"(c[2]), "+f"(c[3])
        : "r"(a[0]), "r"(a[1]), "r"(a[2]), "r"(a[3]), "r"(b[0]), "r"(b[1]));
}

// fp16-accumulator variant: D,C are 2 regs (4 halves). C may differ from D.
__device__ __forceinline__ void mma_f16acc(unsigned* d, const unsigned* a,
                                           const unsigned* b, const unsigned* c) {
    asm volatile(
        "mma.sync.aligned.m16n8k16.row.col.f16.f16.f16.f16 "
        "{%0,%1}, {%2,%3,%4,%5}, {%6,%7}, {%8,%9};\n"
        : "=r"(d[0]), "=r"(d[1])
        : "r"(a[0]), "r"(a[1]), "r"(a[2]), "r"(a[3]),
          "r"(b[0]), "r"(b[1]), "r"(c[0]), "r"(c[1]));
}

// ===========================================================================
// Fused pre-pass: one launch does cvt_x | trans_w | trans_cw, partitioned by
// blockIdx.x.
// ===========================================================================
#define PREP_CVTX   8192
#define PREP_TRW    (PREP_CVTX + 2048)
#define PREP_TOTAL  (PREP_TRW + 4096)

__global__ __launch_bounds__(256)
void prep_kernel(const float* __restrict__ x, const float* __restrict__ W,
                 const float* __restrict__ cw) {
    __shared__ float tile[32][33];
    const int bx = blockIdx.x;
    const int tx = threadIdx.x & 31;
    const int ty = threadIdx.x >> 5;

    if (bx < PREP_CVTX) {
        long i = ((long)bx * 256 + threadIdx.x) * 8;
        float4 v0 = *(const float4*)(x + i);
        float4 v1 = *(const float4*)(x + i + 4);
        __half2* o = (__half2*)(g_xh + i);
        o[0] = __floats2half2_rn(v0.x, v0.y);
        o[1] = __floats2half2_rn(v0.z, v0.w);
        o[2] = __floats2half2_rn(v1.x, v1.y);
        o[3] = __floats2half2_rn(v1.z, v1.w);
    } else if (bx < PREP_TRW) {
        int t  = bx - PREP_CVTX;
        int g  = t >> 7;
        int rem = t & 127;
        int d0 = (rem >> 4) * 32;
        int f0 = (rem & 15) * 32;
        const float* Wg = W + (long)g * FDIM * DDIM;
#pragma unroll
        for (int j = 0; j < 4; j++) {
            int f = ty + j * 8;
            tile[f][tx] = Wg[(long)(f0 + f) * DDIM + d0 + tx];
        }
        __syncthreads();
        __half* dst = g_wT + (long)g * DDIM * FDIM;
#pragma unroll
        for (int j = 0; j < 4; j++) {
            int d = ty + j * 8;
            dst[(long)(d0 + d) * FDIM + f0 + tx] = __float2half_rn(tile[tx][d]);
        }
    } else {
        int t  = bx - PREP_TRW;
        int o0 = (t >> 8) * 32;
        int k0 = (t & 255) * 32;
#pragma unroll
        for (int j = 0; j < 4; j++) {
            int k = ty + j * 8;
            tile[k][tx] = cw[(long)(k0 + k) * OCH + o0 + tx];
        }
        __syncthreads();
#pragma unroll
        for (int j = 0; j < 4; j++) {
            int o = ty + j * 8;
            g_cwT[(long)(o0 + o) * KTOT + k0 + tx] = __float2half_rn(tile[tx][o]);
        }
    }
}

// ===========================================================================
// Kernel 1: gather + grouped GEMM, fp16 m16n8k16 (f32 accum), 2 m-tiles/CTA.
// ===========================================================================
#define BKH 64
#define A_TILE 16384
#define STAGE_B 32768
#define G1_SMEM (3 * STAGE_B + 1024)

__global__ __launch_bounds__(128, 2)
void gemm1_mma_kernel(const int* __restrict__ idx, const float* __restrict__ bias) {
    extern __shared__ __align__(128) char smem[];
    unsigned smem_base;
    asm("{ .reg .u64 t; cvta.to.shared.u64 t, %1; cvt.u32.u64 %0, t; }"
        : "=r"(smem_base) : "l"(smem));
    int* rowbase = (int*)(smem + 3 * STAGE_B);

    const int grp   = blockIdx.z;
    const int mpair = blockIdx.y;
    const int n0    = blockIdx.x * 128;
    const int tid  = threadIdx.x;
    const int lane = tid & 31;
    const int warp = tid >> 5;
    const int wm = warp >> 1;
    const int wn = warp & 1;
    const int gi = lane >> 2;
    const int tl = lane & 3;
    const int grp8 = lane >> 3;
    const int r8   = lane & 7;

#pragma unroll
    for (int j = 0; j < 2; j++) {
        int m  = mpair * 256 + tid + j * 128;
        int bb = m >> 6;
        int s  = m & 63;
        rowbase[tid + j * 128] = bb * NTOK + idx[grp * SEQ + s];
    }
    __syncthreads();

    const __half* Bsrc = g_wT + (long)grp * DDIM * FDIM;

    float acc[4][8][4];
#pragma unroll
    for (int mt = 0; mt < 4; mt++)
#pragma unroll
        for (int nt = 0; nt < 8; nt++)
#pragma unroll
            for (int i = 0; i < 4; i++) acc[mt][nt][i] = 0.f;

    const int NS = 16;

    auto load_stage = [&](int it) {
        const int mt2 = it >> 3;
        const int ks  = (it & 7) * BKH;
        const int buf = it % 3;
        const unsigned abase = smem_base + buf * STAGE_B;
        const unsigned bbase = abase + A_TILE;
#pragma unroll
        for (int i = 0; i < 8; i++) {
            int c   = tid + i * 128;
            int row = c >> 3;
            int ch  = c & 7;
            cp16(abase + row * 128 + ((ch ^ (row & 7)) * 16),
                 g_xh + (long)rowbase[mt2 * 128 + row] * FDIM + ks + ch * 8, 16);
        }
#pragma unroll
        for (int i = 0; i < 8; i++) {
            int c   = tid + i * 128;
            int row = c >> 3;
            int ch  = c & 7;
            cp16(bbase + row * 128 + ((ch ^ (row & 7)) * 16),
                 Bsrc + (long)(n0 + row) * FDIM + ks + ch * 8, 16);
        }
        asm volatile("cp.async.commit_group;\n");
    };

    auto epilogue = [&](int mt2) {
        const int mbase = mpair * 256 + mt2 * 128;
#pragma unroll
        for (int mt = 0; mt < 4; mt++) {
            int r0 = mbase + wm * 64 + mt * 16 + gi;
            int r1 = r0 + 8;
#pragma unroll
            for (int nt = 0; nt < 8; nt++) {
                int c = n0 + wn * 64 + nt * 8 + 2 * tl;
                float2 bv = *(const float2*)(bias + grp * DDIM + c);
                {
                    int bb = r0 >> 6, s = r0 & 63;
                    __half2* dst = (__half2*)(g_mid + ((long)(bb * NTOK + grp * SEQ + s)) * DDIM + c);
                    *dst = __floats2half2_rn(acc[mt][nt][0] + bv.x, acc[mt][nt][1] + bv.y);
                }
                {
                    int bb = r1 >> 6, s = r1 & 63;
                    __half2* dst = (__half2*)(g_mid + ((long)(bb * NTOK + grp * SEQ + s)) * DDIM + c);
                    *dst = __floats2half2_rn(acc[mt][nt][2] + bv.x, acc[mt][nt][3] + bv.y);
                }
                acc[mt][nt][0] = 0.f; acc[mt][nt][1] = 0.f;
                acc[mt][nt][2] = 0.f; acc[mt][nt][3] = 0.f;
            }
        }
    };

    load_stage(0);
    load_stage(1);

#pragma unroll 1
    for (int s = 0; s < NS; s++) {
        if (s + 1 < NS) asm volatile("cp.async.wait_group 1;\n");
        else            asm volatile("cp.async.wait_group 0;\n");
        __syncthreads();

        if (s == 8) epilogue(0);

        if (s + 2 < NS) load_stage(s + 2);

        const int buf = s % 3;
        const unsigned abase = smem_base + buf * STAGE_B;
        const unsigned bbase = abase + A_TILE;

#pragma unroll
        for (int k4 = 0; k4 < 4; k4++) {
            const int kc = k4 * 2;
            unsigned af[4][4];
            unsigned bf[4][4];
#pragma unroll
            for (int mt = 0; mt < 4; mt++) {
                int row = wm * 64 + mt * 16 + (grp8 & 1) * 8 + r8;
                int ch  = kc + (grp8 >> 1);
                ldsm4(af[mt], abase + row * 128 + ((ch ^ (row & 7)) * 16));
            }
#pragma unroll
            for (int q = 0; q < 4; q++) {
                int row = wn * 64 + q * 16 + (grp8 >> 1) * 8 + r8;
                int ch  = kc + (grp8 & 1);
                ldsm4(bf[q], bbase + row * 128 + ((ch ^ (row & 7)) * 16));
            }
#pragma unroll
            for (int mt = 0; mt < 4; mt++)
#pragma unroll
                for (int nt = 0; nt < 8; nt++)
                    mma_f16(acc[mt][nt], af[mt], &bf[nt >> 1][(nt & 1) * 2]);
        }
    }

    epilogue(1);
}

// ===========================================================================
// Kernel 2: conv1d implicit GEMM, fp16 m16n8k16 with FP16 ACCUMULATION
//   within each stage (K=64 = 4 MMAs), spilled into f32 accumulators once
//   per stage (bounds f16 rounding error; tests the 2x f16-accum rate).
//   CTA 128x128, 4 warps (2m x 2n), warp 64x64, BKH=64, 3-stage cp.async.
// ===========================================================================
#define SM_TOTAL_CONV (6 * A_TILE)   // 96 KB

__global__ __launch_bounds__(128, 2)
void conv_mma_kernel(const float* __restrict__ cb, float* __restrict__ y) {
    extern __shared__ __align__(128) char smem[];
    unsigned smem_base;
    asm("{ .reg .u64 t; cvta.to.shared.u64 t, %1; cvt.u32.u64 %0, t; }"
        : "=r"(smem_base) : "l"(smem));

    const int b  = blockIdx.z;
    const int t0 = blockIdx.y * 128;
    const int n0 = blockIdx.x * 128;
    const int tid  = threadIdx.x;
    const int lane = tid & 31;
    const int warp = tid >> 5;
    const int wm = warp >> 1;
    const int wn = warp & 1;
    const int gi = lane >> 2;
    const int tl = lane & 3;
    const int grp8 = lane >> 3;
    const int r8   = lane & 7;

    const __half* midb = g_mid + (long)b * NTOK * DDIM;

    float acc[4][8][4];
#pragma unroll
    for (int mt = 0; mt < 4; mt++)
#pragma unroll
        for (int nt = 0; nt < 8; nt++)
#pragma unroll
            for (int i = 0; i < 4; i++) acc[mt][nt][i] = 0.f;

    const int NS = KTOT / BKH;   // 128

    auto load_stage = [&](int it) {
        const int ks = it * BKH;
        const int w  = ks >> 8;
        const int d0 = ks & 255;
        const int buf = it % 3;
        const unsigned abase = smem_base + buf * STAGE_B;
        const unsigned bbase = abase + A_TILE;
#pragma unroll
        for (int i = 0; i < 8; i++) {
            int c   = tid + i * 128;
            int row = c >> 3;
            int ch  = c & 7;
            int t   = t0 + row + w;
            cp16(abase + row * 128 + ((ch ^ (row & 7)) * 16),
                 midb + (long)t * DDIM + d0 + ch * 8, (t < NTOK) ? 16 : 0);
        }
#pragma unroll
        for (int i = 0; i < 8; i++) {
            int c   = tid + i * 128;
            int row = c >> 3;
            int ch  = c & 7;
            cp16(bbase + row * 128 + ((ch ^ (row & 7)) * 16),
                 g_cwT + (long)(n0 + row) * KTOT + ks + ch * 8, 16);
        }
        asm volatile("cp.async.commit_group;\n");
    };

    load_stage(0);
    load_stage(1);

    const unsigned zz[2] = {0u, 0u};

#pragma unroll 1
    for (int s = 0; s < NS; s++) {
        if (s + 1 < NS) asm volatile("cp.async.wait_group 1;\n");
        else            asm volatile("cp.async.wait_group 0;\n");
        __syncthreads();

        if (s + 2 < NS) load_stage(s + 2);

        const int buf = s % 3;
        const unsigned abase = smem_base + buf * STAGE_B;
        const unsigned bbase = abase + A_TILE;

        unsigned acch[4][8][2];

#pragma unroll
        for (int k4 = 0; k4 < 4; k4++) {
            const int kc = k4 * 2;
            unsigned af[4][4];
            unsigned bf[4][4];
#pragma unroll
            for (int mt = 0; mt < 4; mt++) {
                int row = wm * 64 + mt * 16 + (grp8 & 1) * 8 + r8;
                int ch  = kc + (grp8 >> 1);
                ldsm4(af[mt], abase + row * 128 + ((ch ^ (row & 7)) * 16));
            }
#pragma unroll
            for (int q = 0; q < 4; q++) {
                int row = wn * 64 + q * 16 + (grp8 >> 1) * 8 + r8;
                int ch  = kc + (grp8 & 1);
                ldsm4(bf[q], bbase + row * 128 + ((ch ^ (row & 7)) * 16));
            }
#pragma unroll
            for (int mt = 0; mt < 4; mt++)
#pragma unroll
                for (int nt = 0; nt < 8; nt++)
                    mma_f16acc(acch[mt][nt], af[mt], &bf[nt >> 1][(nt & 1) * 2],
                               (k4 == 0) ? zz : acch[mt][nt]);
        }

        // spill stage-partial f16 sums into f32 accumulators
#pragma unroll
        for (int mt = 0; mt < 4; mt++)
#pragma unroll
            for (int nt = 0; nt < 8; nt++) {
                float2 lo = __half22float2(*(const __half2*)&acch[mt][nt][0]);
                float2 hi = __half22float2(*(const __half2*)&acch[mt][nt][1]);
                acc[mt][nt][0] += lo.x;
                acc[mt][nt][1] += lo.y;
                acc[mt][nt][2] += hi.x;
                acc[mt][nt][3] += hi.y;
            }
    }

    // epilogue: bias + leaky relu
#pragma unroll
    for (int mt = 0; mt < 4; mt++) {
        int r0 = t0 + wm * 64 + mt * 16 + gi;
        int r1 = r0 + 8;
#pragma unroll
        for (int nt = 0; nt < 8; nt++) {
            int c = n0 + wn * 64 + nt * 8 + 2 * tl;
            float2 bv = *(const float2*)(cb + c);
            if (r0 < TOUT) {
                float v0 = acc[mt][nt][0] + bv.x;
                float v1 = acc[mt][nt][1] + bv.y;
                v0 = (v0 >= 0.f) ? v0 : NEG_SLOPE * v0;
                v1 = (v1 >= 0.f) ? v1 : NEG_SLOPE * v1;
                *(float2*)(y + ((long)b * TOUT + r0) * OCH + c) = make_float2(v0, v1);
            }
            if (r1 < TOUT) {
                float v2 = acc[mt][nt][2] + bv.x;
                float v3 = acc[mt][nt][3] + bv.y;
                v2 = (v2 >= 0.f) ? v2 : NEG_SLOPE * v2;
                v3 = (v3 >= 0.f) ? v3 : NEG_SLOPE * v3;
                *(float2*)(y + ((long)b * TOUT + r1) * OCH + c) = make_float2(v2, v3);
            }
        }
    }
}

// ===========================================================================
extern "C" void kernel_launch(void* const* d_in, const int* in_sizes, int n_in,
                              void* d_out, int out_size) {
    const float* x    = (const float*)d_in[0];
    const int*   idx  = (const int*)  d_in[1];
    const float* W    = (const float*)d_in[2];
    const float* bias = (const float*)d_in[3];
    const float* cw   = (const float*)d_in[4];
    const float* cb   = (const float*)d_in[5];
    float* y = (float*)d_out;

    cudaFuncSetAttribute(conv_mma_kernel,
                         cudaFuncAttributeMaxDynamicSharedMemorySize, SM_TOTAL_CONV);
    cudaFuncSetAttribute(gemm1_mma_kernel,
                         cudaFuncAttributeMaxDynamicSharedMemorySize, G1_SMEM);

    prep_kernel<<<PREP_TOTAL, 256>>>(x, W, cw);

    dim3 grid1(DDIM / 128, (BATCH * SEQ) / 256, GRP);   // (2, 8, 16)
    gemm1_mma_kernel<<<grid1, 128, G1_SMEM>>>(idx, bias);

    dim3 grid2(OCH / 128, NTOK / 128, BATCH);           // (4, 8, 32)
    conv_mma_kernel<<<grid2, 128, SM_TOTAL_CONV>>>(cb, y);
}

// round 15
// speedup vs baseline: 1.1655x; 1.1655x over previous
#include <cuda_runtime.h>
#include <cuda_fp16.h>
#include <cstdint>

// Problem constants
#define BATCH 32
#define NTOK  1024
#define FDIM  512
#define GRP   16
#define SEQ   64
#define DDIM  256
#define WIN   32
#define OCH   512
#define TOUT  993          // NTOK - WIN + 1
#define KTOT  (WIN * DDIM) // 8192
#define NEG_SLOPE 0.2f

// Scratch (device globals; no allocs allowed)
__device__ __half g_mid[BATCH * NTOK * DDIM];         // 16 MB, fp16 mid
__device__ __half g_cwT[OCH * KTOT];                  // 8 MB, conv_w transposed [O][K], fp16
__device__ __half g_xh [BATCH * NTOK * FDIM];         // 32 MB, x in fp16
__device__ __half g_wT [GRP * DDIM * FDIM];           // 4 MB, W transposed [g][d][f], fp16

__device__ __forceinline__ void cp16(unsigned smem, const void* g, int sz) {
    asm volatile("cp.async.ca.shared.global [%0], [%1], 16, %2;\n"
                 :: "r"(smem), "l"(g), "r"(sz));
}

__device__ __forceinline__ void ldsm4(unsigned* r, unsigned addr) {
    asm volatile("ldmatrix.sync.aligned.m8n8.x4.shared.b16 {%0,%1,%2,%3}, [%4];"
                 : "=r"(r[0]), "=r"(r[1]), "=r"(r[2]), "=r"(r[3]) : "r"(addr));
}

__device__ __forceinline__ void mma_f16(float* c, const unsigned* a, const unsigned* b) {
    asm volatile(
        "mma.sync.aligned.m16n8k16.row.col.f32.f16.f16.f32 "
        "{%0,%1,%2,%3}, {%4,%5,%6,%7}, {%8,%9}, {%0,%1,%2,%3};\n"
        : "+f"(c[0]), "+f"(c[1]), "+f"(c[2]), "+f"(c[3])
        : "r"(a[0]), "r"(a[1]), "r"(a[2]), "r"(a[3]), "r"(b[0]), "r"(b[1]));
}

// ===========================================================================
// Pre-pass: cvt_x | trans_w (trans_cw moved into the gemm1 launch).
//   [0, 8192)        cvt_x   : x fp32 -> g_xh fp16 (8 elems/thread)
//   [8192, 10240)    trans_w : W [g][f][d] -> g_wT [g][d][f] fp16
// ===========================================================================
#define PREP_CVTX   8192
#define PREP_TOTAL  (PREP_CVTX + 2048)

__global__ __launch_bounds__(256)
void prep_kernel(const float* __restrict__ x, const float* __restrict__ W) {
    __shared__ float tile[32][33];
    const int bx = blockIdx.x;
    const int tx = threadIdx.x & 31;
    const int ty = threadIdx.x >> 5;

    if (bx < PREP_CVTX) {
        long i = ((long)bx * 256 + threadIdx.x) * 8;
        float4 v0 = *(const float4*)(x + i);
        float4 v1 = *(const float4*)(x + i + 4);
        __half2* o = (__half2*)(g_xh + i);
        o[0] = __floats2half2_rn(v0.x, v0.y);
        o[1] = __floats2half2_rn(v0.z, v0.w);
        o[2] = __floats2half2_rn(v1.x, v1.y);
        o[3] = __floats2half2_rn(v1.z, v1.w);
    } else {
        int t  = bx - PREP_CVTX;
        int g  = t >> 7;
        int rem = t & 127;
        int d0 = (rem >> 4) * 32;
        int f0 = (rem & 15) * 32;
        const float* Wg = W + (long)g * FDIM * DDIM;
#pragma unroll
        for (int j = 0; j < 4; j++) {
            int f = ty + j * 8;
            tile[f][tx] = Wg[(long)(f0 + f) * DDIM + d0 + tx];
        }
        __syncthreads();
        __half* dst = g_wT + (long)g * DDIM * FDIM;
#pragma unroll
        for (int j = 0; j < 4; j++) {
            int d = ty + j * 8;
            dst[(long)(d0 + d) * FDIM + f0 + tx] = __float2half_rn(tile[tx][d]);
        }
    }
}

// ===========================================================================
// Kernel 1 (combined launch): 1-D grid.
//   bx <  256 : gather + grouped GEMM, fp16 m16n8k16, 2 m-tiles/CTA.
//               decode: n0 = (bx&1)*128, mpair = (bx>>1)&7, grp = bx>>4.
//   bx >= 256 : trans_cw tile (cw [K][O] -> g_cwT [O][K] fp16); these blocks
//               fill gemm1's idle wave slots and its tail.
// ===========================================================================
#define BKH 64
#define A_TILE 16384
#define STAGE_B 32768
#define G1_SMEM (3 * STAGE_B + 1024)
#define G1_GEMM 256
#define G1_TOTAL (G1_GEMM + 4096)

__global__ __launch_bounds__(128, 2)
void gemm1_mma_kernel(const int* __restrict__ idx, const float* __restrict__ bias,
                      const float* __restrict__ cw) {
    extern __shared__ __align__(128) char smem[];

    const int bx = blockIdx.x;
    const int tid  = threadIdx.x;

    if (bx >= G1_GEMM) {
        // ---- trans_cw tile: 16 o-blocks x 256 k-blocks, 128 threads ----
        float (*tile)[33] = (float(*)[33])smem;
        int t  = bx - G1_GEMM;
        int o0 = (t >> 8) * 32;
        int k0 = (t & 255) * 32;
        const int tx = tid & 31;
        const int ty = tid >> 5;           // 0..3
#pragma unroll
        for (int j = 0; j < 8; j++) {
            int k = ty + j * 4;
            tile[k][tx] = cw[(long)(k0 + k) * OCH + o0 + tx];
        }
        __syncthreads();
#pragma unroll
        for (int j = 0; j < 8; j++) {
            int o = ty + j * 4;
            g_cwT[(long)(o0 + o) * KTOT + k0 + tx] = __float2half_rn(tile[tx][o]);
        }
        return;
    }

    // ---- GEMM CTA ----
    unsigned smem_base;
    asm("{ .reg .u64 t; cvta.to.shared.u64 t, %1; cvt.u32.u64 %0, t; }"
        : "=r"(smem_base) : "l"(smem));
    int* rowbase = (int*)(smem + 3 * STAGE_B);

    const int grp   = bx >> 4;
    const int mpair = (bx >> 1) & 7;
    const int n0    = (bx & 1) * 128;
    const int lane = tid & 31;
    const int warp = tid >> 5;
    const int wm = warp >> 1;
    const int wn = warp & 1;
    const int gi = lane >> 2;
    const int tl = lane & 3;
    const int grp8 = lane >> 3;
    const int r8   = lane & 7;

#pragma unroll
    for (int j = 0; j < 2; j++) {
        int m  = mpair * 256 + tid + j * 128;
        int bb = m >> 6;
        int s  = m & 63;
        rowbase[tid + j * 128] = bb * NTOK + idx[grp * SEQ + s];
    }
    __syncthreads();

    const __half* Bsrc = g_wT + (long)grp * DDIM * FDIM;

    float acc[4][8][4];
#pragma unroll
    for (int mt = 0; mt < 4; mt++)
#pragma unroll
        for (int nt = 0; nt < 8; nt++)
#pragma unroll
            for (int i = 0; i < 4; i++) acc[mt][nt][i] = 0.f;

    const int NS = 16;

    auto load_stage = [&](int it) {
        const int mt2 = it >> 3;
        const int ks  = (it & 7) * BKH;
        const int buf = it % 3;
        const unsigned abase = smem_base + buf * STAGE_B;
        const unsigned bbase = abase + A_TILE;
#pragma unroll
        for (int i = 0; i < 8; i++) {
            int c   = tid + i * 128;
            int row = c >> 3;
            int ch  = c & 7;
            cp16(abase + row * 128 + ((ch ^ (row & 7)) * 16),
                 g_xh + (long)rowbase[mt2 * 128 + row] * FDIM + ks + ch * 8, 16);
        }
#pragma unroll
        for (int i = 0; i < 8; i++) {
            int c   = tid + i * 128;
            int row = c >> 3;
            int ch  = c & 7;
            cp16(bbase + row * 128 + ((ch ^ (row & 7)) * 16),
                 Bsrc + (long)(n0 + row) * FDIM + ks + ch * 8, 16);
        }
        asm volatile("cp.async.commit_group;\n");
    };

    auto epilogue = [&](int mt2) {
        const int mbase = mpair * 256 + mt2 * 128;
#pragma unroll
        for (int mt = 0; mt < 4; mt++) {
            int r0 = mbase + wm * 64 + mt * 16 + gi;
            int r1 = r0 + 8;
#pragma unroll
            for (int nt = 0; nt < 8; nt++) {
                int c = n0 + wn * 64 + nt * 8 + 2 * tl;
                float2 bv = *(const float2*)(bias + grp * DDIM + c);
                {
                    int bb = r0 >> 6, s = r0 & 63;
                    __half2* dst = (__half2*)(g_mid + ((long)(bb * NTOK + grp * SEQ + s)) * DDIM + c);
                    *dst = __floats2half2_rn(acc[mt][nt][0] + bv.x, acc[mt][nt][1] + bv.y);
                }
                {
                    int bb = r1 >> 6, s = r1 & 63;
                    __half2* dst = (__half2*)(g_mid + ((long)(bb * NTOK + grp * SEQ + s)) * DDIM + c);
                    *dst = __floats2half2_rn(acc[mt][nt][2] + bv.x, acc[mt][nt][3] + bv.y);
                }
                acc[mt][nt][0] = 0.f; acc[mt][nt][1] = 0.f;
                acc[mt][nt][2] = 0.f; acc[mt][nt][3] = 0.f;
            }
        }
    };

    load_stage(0);
    load_stage(1);

#pragma unroll 1
    for (int s = 0; s < NS; s++) {
        if (s + 1 < NS) asm volatile("cp.async.wait_group 1;\n");
        else            asm volatile("cp.async.wait_group 0;\n");
        __syncthreads();

        if (s == 8) epilogue(0);

        if (s + 2 < NS) load_stage(s + 2);

        const int buf = s % 3;
        const unsigned abase = smem_base + buf * STAGE_B;
        const unsigned bbase = abase + A_TILE;

#pragma unroll
        for (int k4 = 0; k4 < 4; k4++) {
            const int kc = k4 * 2;
            unsigned af[4][4];
            unsigned bf[4][4];
#pragma unroll
            for (int mt = 0; mt < 4; mt++) {
                int row = wm * 64 + mt * 16 + (grp8 & 1) * 8 + r8;
                int ch  = kc + (grp8 >> 1);
                ldsm4(af[mt], abase + row * 128 + ((ch ^ (row & 7)) * 16));
            }
#pragma unroll
            for (int q = 0; q < 4; q++) {
                int row = wn * 64 + q * 16 + (grp8 >> 1) * 8 + r8;
                int ch  = kc + (grp8 & 1);
                ldsm4(bf[q], bbase + row * 128 + ((ch ^ (row & 7)) * 16));
            }
#pragma unroll
            for (int mt = 0; mt < 4; mt++)
#pragma unroll
                for (int nt = 0; nt < 8; nt++)
                    mma_f16(acc[mt][nt], af[mt], &bf[nt >> 1][(nt & 1) * 2]);
        }
    }

    epilogue(1);
}

// ===========================================================================
// Kernel 2: conv1d implicit GEMM, fp16 m16n8k16, f32 accum — R13/R7 version.
//   CTA 128x128, 4 warps (2m x 2n), warp 64x64, BKH=64, 3-stage cp.async.
//   Rows 128B; 16B chunks XOR-swizzled; fragment double-buffering.
// ===========================================================================
#define SM_TOTAL_CONV (6 * A_TILE)   // 96 KB

__global__ __launch_bounds__(128, 2)
void conv_mma_kernel(const float* __restrict__ cb, float* __restrict__ y) {
    extern __shared__ __align__(128) char smem[];
    unsigned smem_base;
    asm("{ .reg .u64 t; cvta.to.shared.u64 t, %1; cvt.u32.u64 %0, t; }"
        : "=r"(smem_base) : "l"(smem));

    const int b  = blockIdx.z;
    const int t0 = blockIdx.y * 128;
    const int n0 = blockIdx.x * 128;
    const int tid  = threadIdx.x;
    const int lane = tid & 31;
    const int warp = tid >> 5;
    const int wm = warp >> 1;
    const int wn = warp & 1;
    const int gi = lane >> 2;
    const int tl = lane & 3;
    const int grp8 = lane >> 3;
    const int r8   = lane & 7;

    const __half* midb = g_mid + (long)b * NTOK * DDIM;

    float acc[4][8][4];
#pragma unroll
    for (int mt = 0; mt < 4; mt++)
#pragma unroll
        for (int nt = 0; nt < 8; nt++)
#pragma unroll
            for (int i = 0; i < 4; i++) acc[mt][nt][i] = 0.f;

    const int NS = KTOT / BKH;   // 128

    auto load_stage = [&](int it) {
        const int ks = it * BKH;
        const int w  = ks >> 8;
        const int d0 = ks & 255;
        const int buf = it % 3;
        const unsigned abase = smem_base + buf * STAGE_B;
        const unsigned bbase = abase + A_TILE;
#pragma unroll
        for (int i = 0; i < 8; i++) {
            int c   = tid + i * 128;
            int row = c >> 3;
            int ch  = c & 7;
            int t   = t0 + row + w;
            cp16(abase + row * 128 + ((ch ^ (row & 7)) * 16),
                 midb + (long)t * DDIM + d0 + ch * 8, (t < NTOK) ? 16 : 0);
        }
#pragma unroll
        for (int i = 0; i < 8; i++) {
            int c   = tid + i * 128;
            int row = c >> 3;
            int ch  = c & 7;
            cp16(bbase + row * 128 + ((ch ^ (row & 7)) * 16),
                 g_cwT + (long)(n0 + row) * KTOT + ks + ch * 8, 16);
        }
        asm volatile("cp.async.commit_group;\n");
    };

    auto ldfrag = [&](unsigned af[4][4], unsigned bf[4][4],
                      int kc, unsigned abase, unsigned bbase) {
#pragma unroll
        for (int mt = 0; mt < 4; mt++) {
            int row = wm * 64 + mt * 16 + (grp8 & 1) * 8 + r8;
            int ch  = kc + (grp8 >> 1);
            ldsm4(af[mt], abase + row * 128 + ((ch ^ (row & 7)) * 16));
        }
#pragma unroll
        for (int q = 0; q < 4; q++) {
            int row = wn * 64 + q * 16 + (grp8 >> 1) * 8 + r8;
            int ch  = kc + (grp8 & 1);
            ldsm4(bf[q], bbase + row * 128 + ((ch ^ (row & 7)) * 16));
        }
    };

    load_stage(0);
    load_stage(1);

    unsigned af[2][4][4];
    unsigned bf[2][4][4];

#pragma unroll 1
    for (int s = 0; s < NS; s++) {
        if (s + 1 < NS) asm volatile("cp.async.wait_group 1;\n");
        else            asm volatile("cp.async.wait_group 0;\n");
        __syncthreads();

        if (s + 2 < NS) load_stage(s + 2);

        const int buf = s % 3;
        const unsigned abase = smem_base + buf * STAGE_B;
        const unsigned bbase = abase + A_TILE;

        ldfrag(af[0], bf[0], 0, abase, bbase);

#pragma unroll
        for (int k4 = 0; k4 < 4; k4++) {
            const int cur = k4 & 1;
            if (k4 < 3)
                ldfrag(af[cur ^ 1], bf[cur ^ 1], (k4 + 1) * 2, abase, bbase);
#pragma unroll
            for (int mt = 0; mt < 4; mt++)
#pragma unroll
                for (int nt = 0; nt < 8; nt++)
                    mma_f16(acc[mt][nt], af[cur][mt], &bf[cur][nt >> 1][(nt & 1) * 2]);
        }
    }

    // epilogue: bias + leaky relu
#pragma unroll
    for (int mt = 0; mt < 4; mt++) {
        int r0 = t0 + wm * 64 + mt * 16 + gi;
        int r1 = r0 + 8;
#pragma unroll
        for (int nt = 0; nt < 8; nt++) {
            int c = n0 + wn * 64 + nt * 8 + 2 * tl;
            float2 bv = *(const float2*)(cb + c);
            if (r0 < TOUT) {
                float v0 = acc[mt][nt][0] + bv.x;
                float v1 = acc[mt][nt][1] + bv.y;
                v0 = (v0 >= 0.f) ? v0 : NEG_SLOPE * v0;
                v1 = (v1 >= 0.f) ? v1 : NEG_SLOPE * v1;
                *(float2*)(y + ((long)b * TOUT + r0) * OCH + c) = make_float2(v0, v1);
            }
            if (r1 < TOUT) {
                float v2 = acc[mt][nt][2] + bv.x;
                float v3 = acc[mt][nt][3] + bv.y;
                v2 = (v2 >= 0.f) ? v2 : NEG_SLOPE * v2;
                v3 = (v3 >= 0.f) ? v3 : NEG_SLOPE * v3;
                *(float2*)(y + ((long)b * TOUT + r1) * OCH + c) = make_float2(v2, v3);
            }
        }
    }
}

// ===========================================================================
extern "C" void kernel_launch(void* const* d_in, const int* in_sizes, int n_in,
                              void* d_out, int out_size) {
    const float* x    = (const float*)d_in[0];
    const int*   idx  = (const int*)  d_in[1];
    const float* W    = (const float*)d_in[2];
    const float* bias = (const float*)d_in[3];
    const float* cw   = (const float*)d_in[4];
    const float* cb   = (const float*)d_in[5];
    float* y = (float*)d_out;

    cudaFuncSetAttribute(conv_mma_kernel,
                         cudaFuncAttributeMaxDynamicSharedMemorySize, SM_TOTAL_CONV);
    cudaFuncSetAttribute(gemm1_mma_kernel,
                         cudaFuncAttributeMaxDynamicSharedMemorySize, G1_SMEM);

    prep_kernel<<<PREP_TOTAL, 256>>>(x, W);

    gemm1_mma_kernel<<<G1_TOTAL, 128, G1_SMEM>>>(idx, bias, cw);

    dim3 grid2(OCH / 128, NTOK / 128, BATCH);           // (4, 8, 32)
    conv_mma_kernel<<<grid2, 128, SM_TOTAL_CONV>>>(cb, y);
}

// round 16
// speedup vs baseline: 1.1667x; 1.0010x over previous
#include <cuda_runtime.h>
#include <cuda_fp16.h>
#include <cstdint>

// Problem constants
#define BATCH 32
#define NTOK  1024
#define FDIM  512
#define GRP   16
#define SEQ   64
#define DDIM  256
#define WIN   32
#define OCH   512
#define TOUT  993          // NTOK - WIN + 1
#define KTOT  (WIN * DDIM) // 8192
#define NEG_SLOPE 0.2f

// Scratch (device globals; no allocs allowed)
__device__ __half g_mid[BATCH * NTOK * DDIM];         // 16 MB, fp16 mid
__device__ __half g_cwT[OCH * KTOT];                  // 8 MB, conv_w transposed [O][K], fp16
__device__ __half g_xh [BATCH * NTOK * FDIM];         // 32 MB, x in fp16
__device__ __half g_wT [GRP * DDIM * FDIM];           // 4 MB, W transposed [g][d][f], fp16

__device__ __forceinline__ void cp16(unsigned smem, const void* g, int sz) {
    asm volatile("cp.async.ca.shared.global [%0], [%1], 16, %2;\n"
                 :: "r"(smem), "l"(g), "r"(sz));
}

__device__ __forceinline__ void ldsm4(unsigned* r, unsigned addr) {
    asm volatile("ldmatrix.sync.aligned.m8n8.x4.shared.b16 {%0,%1,%2,%3}, [%4];"
                 : "=r"(r[0]), "=r"(r[1]), "=r"(r[2]), "=r"(r[3]) : "r"(addr));
}

__device__ __forceinline__ void mma_f16(float* c, const unsigned* a, const unsigned* b) {
    asm volatile(
        "mma.sync.aligned.m16n8k16.row.col.f32.f16.f16.f32 "
        "{%0,%1,%2,%3}, {%4,%5,%6,%7}, {%8,%9}, {%0,%1,%2,%3};\n"
        : "+f"(c[0]), "+f"(c[1]), "+f"(c[2]), "+f"(c[3])
        : "r"(a[0]), "r"(a[1]), "r"(a[2]), "r"(a[3]), "r"(b[0]), "r"(b[1]));
}

// ===========================================================================
// Fused pre-pass (R13): cvt_x | trans_w | trans_cw, partitioned by blockIdx.x.
// ===========================================================================
#define PREP_CVTX   8192
#define PREP_TRW    (PREP_CVTX + 2048)
#define PREP_TOTAL  (PREP_TRW + 4096)

__global__ __launch_bounds__(256)
void prep_kernel(const float* __restrict__ x, const float* __restrict__ W,
                 const float* __restrict__ cw) {
    __shared__ float tile[32][33];
    const int bx = blockIdx.x;
    const int tx = threadIdx.x & 31;
    const int ty = threadIdx.x >> 5;

    if (bx < PREP_CVTX) {
        long i = ((long)bx * 256 + threadIdx.x) * 8;
        float4 v0 = *(const float4*)(x + i);
        float4 v1 = *(const float4*)(x + i + 4);
        __half2* o = (__half2*)(g_xh + i);
        o[0] = __floats2half2_rn(v0.x, v0.y);
        o[1] = __floats2half2_rn(v0.z, v0.w);
        o[2] = __floats2half2_rn(v1.x, v1.y);
        o[3] = __floats2half2_rn(v1.z, v1.w);
    } else if (bx < PREP_TRW) {
        int t  = bx - PREP_CVTX;
        int g  = t >> 7;
        int rem = t & 127;
        int d0 = (rem >> 4) * 32;
        int f0 = (rem & 15) * 32;
        const float* Wg = W + (long)g * FDIM * DDIM;
#pragma unroll
        for (int j = 0; j < 4; j++) {
            int f = ty + j * 8;
            tile[f][tx] = Wg[(long)(f0 + f) * DDIM + d0 + tx];
        }
        __syncthreads();
        __half* dst = g_wT + (long)g * DDIM * FDIM;
#pragma unroll
        for (int j = 0; j < 4; j++) {
            int d = ty + j * 8;
            dst[(long)(d0 + d) * FDIM + f0 + tx] = __float2half_rn(tile[tx][d]);
        }
    } else {
        int t  = bx - PREP_TRW;
        int o0 = (t >> 8) * 32;
        int k0 = (t & 255) * 32;
#pragma unroll
        for (int j = 0; j < 4; j++) {
            int k = ty + j * 8;
            tile[k][tx] = cw[(long)(k0 + k) * OCH + o0 + tx];
        }
        __syncthreads();
#pragma unroll
        for (int j = 0; j < 4; j++) {
            int o = ty + j * 8;
            g_cwT[(long)(o0 + o) * KTOT + k0 + tx] = __float2half_rn(tile[tx][o]);
        }
    }
}

// ===========================================================================
// Kernel 1: gather + grouped GEMM, fp16 m16n8k16.
//   CTA 128x128 per m-tile, 2 m-tiles/CTA (16 stages, mid epilogue at s==8).
//   256 threads, 8 warps (2m x 4n), warp 64x32 -> acc 64 regs ->
//   __launch_bounds__(256,2) = 16 warps/SM for latency hiding on short K.
// ===========================================================================
#define BKH 64
#define A_TILE 16384
#define STAGE_B 32768
#define G1_SMEM (3 * STAGE_B + 1024)

__global__ __launch_bounds__(256, 2)
void gemm1_mma_kernel(const int* __restrict__ idx, const float* __restrict__ bias) {
    extern __shared__ __align__(128) char smem[];
    unsigned smem_base;
    asm("{ .reg .u64 t; cvta.to.shared.u64 t, %1; cvt.u32.u64 %0, t; }"
        : "=r"(smem_base) : "l"(smem));
    int* rowbase = (int*)(smem + 3 * STAGE_B);   // 256 ints

    const int grp   = blockIdx.z;
    const int mpair = blockIdx.y;            // rows [mpair*256, +256)
    const int n0    = blockIdx.x * 128;
    const int tid  = threadIdx.x;
    const int lane = tid & 31;
    const int warp = tid >> 5;
    const int wm = warp & 1;                 // 0..1 -> m offset wm*64
    const int wn = warp >> 1;                // 0..3 -> n offset wn*32
    const int gi = lane >> 2;
    const int tl = lane & 3;
    const int grp8 = lane >> 3;
    const int r8   = lane & 7;

    {
        int m  = mpair * 256 + tid;
        int bb = m >> 6;
        int s  = m & 63;
        rowbase[tid] = bb * NTOK + idx[grp * SEQ + s];
    }
    __syncthreads();

    const __half* Bsrc = g_wT + (long)grp * DDIM * FDIM;

    float acc[4][4][4];
#pragma unroll
    for (int mt = 0; mt < 4; mt++)
#pragma unroll
        for (int nt = 0; nt < 4; nt++)
#pragma unroll
            for (int i = 0; i < 4; i++) acc[mt][nt][i] = 0.f;

    const int NS = 16;   // 2 m-tiles x 8 k-stages

    auto load_stage = [&](int it) {
        const int mt2 = it >> 3;
        const int ks  = (it & 7) * BKH;
        const int buf = it % 3;
        const unsigned abase = smem_base + buf * STAGE_B;
        const unsigned bbase = abase + A_TILE;
#pragma unroll
        for (int i = 0; i < 4; i++) {
            int c   = tid + i * 256;
            int row = c >> 3;
            int ch  = c & 7;
            cp16(abase + row * 128 + ((ch ^ (row & 7)) * 16),
                 g_xh + (long)rowbase[mt2 * 128 + row] * FDIM + ks + ch * 8, 16);
        }
#pragma unroll
        for (int i = 0; i < 4; i++) {
            int c   = tid + i * 256;
            int row = c >> 3;
            int ch  = c & 7;
            cp16(bbase + row * 128 + ((ch ^ (row & 7)) * 16),
                 Bsrc + (long)(n0 + row) * FDIM + ks + ch * 8, 16);
        }
        asm volatile("cp.async.commit_group;\n");
    };

    auto epilogue = [&](int mt2) {
        const int mbase = mpair * 256 + mt2 * 128;
#pragma unroll
        for (int mt = 0; mt < 4; mt++) {
            int r0 = mbase + wm * 64 + mt * 16 + gi;
            int r1 = r0 + 8;
#pragma unroll
            for (int nt = 0; nt < 4; nt++) {
                int c = n0 + wn * 32 + nt * 8 + 2 * tl;
                float2 bv = *(const float2*)(bias + grp * DDIM + c);
                {
                    int bb = r0 >> 6, s = r0 & 63;
                    __half2* dst = (__half2*)(g_mid + ((long)(bb * NTOK + grp * SEQ + s)) * DDIM + c);
                    *dst = __floats2half2_rn(acc[mt][nt][0] + bv.x, acc[mt][nt][1] + bv.y);
                }
                {
                    int bb = r1 >> 6, s = r1 & 63;
                    __half2* dst = (__half2*)(g_mid + ((long)(bb * NTOK + grp * SEQ + s)) * DDIM + c);
                    *dst = __floats2half2_rn(acc[mt][nt][2] + bv.x, acc[mt][nt][3] + bv.y);
                }
                acc[mt][nt][0] = 0.f; acc[mt][nt][1] = 0.f;
                acc[mt][nt][2] = 0.f; acc[mt][nt][3] = 0.f;
            }
        }
    };

    load_stage(0);
    load_stage(1);

#pragma unroll 1
    for (int s = 0; s < NS; s++) {
        if (s + 1 < NS) asm volatile("cp.async.wait_group 1;\n");
        else            asm volatile("cp.async.wait_group 0;\n");
        __syncthreads();

        if (s == 8) epilogue(0);

        if (s + 2 < NS) load_stage(s + 2);

        const int buf = s % 3;
        const unsigned abase = smem_base + buf * STAGE_B;
        const unsigned bbase = abase + A_TILE;

#pragma unroll
        for (int k4 = 0; k4 < 4; k4++) {
            const int kc = k4 * 2;
            unsigned af[4][4];
            unsigned bf[2][4];
#pragma unroll
            for (int mt = 0; mt < 4; mt++) {
                int row = wm * 64 + mt * 16 + (grp8 & 1) * 8 + r8;
                int ch  = kc + (grp8 >> 1);
                ldsm4(af[mt], abase + row * 128 + ((ch ^ (row & 7)) * 16));
            }
#pragma unroll
            for (int q = 0; q < 2; q++) {
                int row = wn * 32 + q * 16 + (grp8 >> 1) * 8 + r8;
                int ch  = kc + (grp8 & 1);
                ldsm4(bf[q], bbase + row * 128 + ((ch ^ (row & 7)) * 16));
            }
#pragma unroll
            for (int mt = 0; mt < 4; mt++)
#pragma unroll
                for (int nt = 0; nt < 4; nt++)
                    mma_f16(acc[mt][nt], af[mt], &bf[nt >> 1][(nt & 1) * 2]);
        }
    }

    epilogue(1);
}

// ===========================================================================
// Kernel 2: conv1d implicit GEMM, fp16 m16n8k16, f32 accum — R7/R13 version,
//   UNCHANGED (at the legacy-HMMA instruction-rate floor).
// ===========================================================================
#define SM_TOTAL_CONV (6 * A_TILE)   // 96 KB

__global__ __launch_bounds__(128, 2)
void conv_mma_kernel(const float* __restrict__ cb, float* __restrict__ y) {
    extern __shared__ __align__(128) char smem[];
    unsigned smem_base;
    asm("{ .reg .u64 t; cvta.to.shared.u64 t, %1; cvt.u32.u64 %0, t; }"
        : "=r"(smem_base) : "l"(smem));

    const int b  = blockIdx.z;
    const int t0 = blockIdx.y * 128;
    const int n0 = blockIdx.x * 128;
    const int tid  = threadIdx.x;
    const int lane = tid & 31;
    const int warp = tid >> 5;
    const int wm = warp >> 1;
    const int wn = warp & 1;
    const int gi = lane >> 2;
    const int tl = lane & 3;
    const int grp8 = lane >> 3;
    const int r8   = lane & 7;

    const __half* midb = g_mid + (long)b * NTOK * DDIM;

    float acc[4][8][4];
#pragma unroll
    for (int mt = 0; mt < 4; mt++)
#pragma unroll
        for (int nt = 0; nt < 8; nt++)
#pragma unroll
            for (int i = 0; i < 4; i++) acc[mt][nt][i] = 0.f;

    const int NS = KTOT / BKH;   // 128

    auto load_stage = [&](int it) {
        const int ks = it * BKH;
        const int w  = ks >> 8;
        const int d0 = ks & 255;
        const int buf = it % 3;
        const unsigned abase = smem_base + buf * STAGE_B;
        const unsigned bbase = abase + A_TILE;
#pragma unroll
        for (int i = 0; i < 8; i++) {
            int c   = tid + i * 128;
            int row = c >> 3;
            int ch  = c & 7;
            int t   = t0 + row + w;
            cp16(abase + row * 128 + ((ch ^ (row & 7)) * 16),
                 midb + (long)t * DDIM + d0 + ch * 8, (t < NTOK) ? 16 : 0);
        }
#pragma unroll
        for (int i = 0; i < 8; i++) {
            int c   = tid + i * 128;
            int row = c >> 3;
            int ch  = c & 7;
            cp16(bbase + row * 128 + ((ch ^ (row & 7)) * 16),
                 g_cwT + (long)(n0 + row) * KTOT + ks + ch * 8, 16);
        }
        asm volatile("cp.async.commit_group;\n");
    };

    auto ldfrag = [&](unsigned af[4][4], unsigned bf[4][4],
                      int kc, unsigned abase, unsigned bbase) {
#pragma unroll
        for (int mt = 0; mt < 4; mt++) {
            int row = wm * 64 + mt * 16 + (grp8 & 1) * 8 + r8;
            int ch  = kc + (grp8 >> 1);
            ldsm4(af[mt], abase + row * 128 + ((ch ^ (row & 7)) * 16));
        }
#pragma unroll
        for (int q = 0; q < 4; q++) {
            int row = wn * 64 + q * 16 + (grp8 >> 1) * 8 + r8;
            int ch  = kc + (grp8 & 1);
            ldsm4(bf[q], bbase + row * 128 + ((ch ^ (row & 7)) * 16));
        }
    };

    load_stage(0);
    load_stage(1);

    unsigned af[2][4][4];
    unsigned bf[2][4][4];

#pragma unroll 1
    for (int s = 0; s < NS; s++) {
        if (s + 1 < NS) asm volatile("cp.async.wait_group 1;\n");
        else            asm volatile("cp.async.wait_group 0;\n");
        __syncthreads();

        if (s + 2 < NS) load_stage(s + 2);

        const int buf = s % 3;
        const unsigned abase = smem_base + buf * STAGE_B;
        const unsigned bbase = abase + A_TILE;

        ldfrag(af[0], bf[0], 0, abase, bbase);

#pragma unroll
        for (int k4 = 0; k4 < 4; k4++) {
            const int cur = k4 & 1;
            if (k4 < 3)
                ldfrag(af[cur ^ 1], bf[cur ^ 1], (k4 + 1) * 2, abase, bbase);
#pragma unroll
            for (int mt = 0; mt < 4; mt++)
#pragma unroll
                for (int nt = 0; nt < 8; nt++)
                    mma_f16(acc[mt][nt], af[cur][mt], &bf[cur][nt >> 1][(nt & 1) * 2]);
        }
    }

    // epilogue: bias + leaky relu
#pragma unroll
    for (int mt = 0; mt < 4; mt++) {
        int r0 = t0 + wm * 64 + mt * 16 + gi;
        int r1 = r0 + 8;
#pragma unroll
        for (int nt = 0; nt < 8; nt++) {
            int c = n0 + wn * 64 + nt * 8 + 2 * tl;
            float2 bv = *(const float2*)(cb + c);
            if (r0 < TOUT) {
                float v0 = acc[mt][nt][0] + bv.x;
                float v1 = acc[mt][nt][1] + bv.y;
                v0 = (v0 >= 0.f) ? v0 : NEG_SLOPE * v0;
                v1 = (v1 >= 0.f) ? v1 : NEG_SLOPE * v1;
                *(float2*)(y + ((long)b * TOUT + r0) * OCH + c) = make_float2(v0, v1);
            }
            if (r1 < TOUT) {
                float v2 = acc[mt][nt][2] + bv.x;
                float v3 = acc[mt][nt][3] + bv.y;
                v2 = (v2 >= 0.f) ? v2 : NEG_SLOPE * v2;
                v3 = (v3 >= 0.f) ? v3 : NEG_SLOPE * v3;
                *(float2*)(y + ((long)b * TOUT + r1) * OCH + c) = make_float2(v2, v3);
            }
        }
    }
}

// ===========================================================================
extern "C" void kernel_launch(void* const* d_in, const int* in_sizes, int n_in,
                              void* d_out, int out_size) {
    const float* x    = (const float*)d_in[0];
    const int*   idx  = (const int*)  d_in[1];
    const float* W    = (const float*)d_in[2];
    const float* bias = (const float*)d_in[3];
    const float* cw   = (const float*)d_in[4];
    const float* cb   = (const float*)d_in[5];
    float* y = (float*)d_out;

    cudaFuncSetAttribute(conv_mma_kernel,
                         cudaFuncAttributeMaxDynamicSharedMemorySize, SM_TOTAL_CONV);
    cudaFuncSetAttribute(gemm1_mma_kernel,
                         cudaFuncAttributeMaxDynamicSharedMemorySize, G1_SMEM);

    prep_kernel<<<PREP_TOTAL, 256>>>(x, W, cw);

    dim3 grid1(DDIM / 128, (BATCH * SEQ) / 256, GRP);   // (2, 8, 16) = 256 CTAs
    gemm1_mma_kernel<<<grid1, 256, G1_SMEM>>>(idx, bias);

    dim3 grid2(OCH / 128, NTOK / 128, BATCH);           // (4, 8, 32)
    conv_mma_kernel<<<grid2, 128, SM_TOTAL_CONV>>>(cb, y);
}

// round 17
// speedup vs baseline: 1.2014x; 1.0297x over previous
#include <cuda_runtime.h>
#include <cuda_fp16.h>
#include <cstdint>

// Problem constants
#define BATCH 32
#define NTOK  1024
#define FDIM  512
#define GRP   16
#define SEQ   64
#define DDIM  256
#define WIN   32
#define OCH   512
#define TOUT  993          // NTOK - WIN + 1
#define KTOT  (WIN * DDIM) // 8192
#define NEG_SLOPE 0.2f

// Scratch (device globals; no allocs allowed)
__device__ __half g_mid[BATCH * NTOK * DDIM];         // 16 MB, fp16 mid
__device__ __half g_cwT[OCH * KTOT];                  // 8 MB, conv_w transposed [O][K], fp16
__device__ __half g_xh [BATCH * NTOK * FDIM];         // 32 MB, x in fp16
__device__ __half g_wT [GRP * DDIM * FDIM];           // 4 MB, W transposed [g][d][f], fp16
__device__ unsigned g_done;                           // gemm1 completion counter

__device__ __forceinline__ void cp16(unsigned smem, const void* g, int sz) {
    asm volatile("cp.async.ca.shared.global [%0], [%1], 16, %2;\n"
                 :: "r"(smem), "l"(g), "r"(sz));
}

__device__ __forceinline__ void ldsm4(unsigned* r, unsigned addr) {
    asm volatile("ldmatrix.sync.aligned.m8n8.x4.shared.b16 {%0,%1,%2,%3}, [%4];"
                 : "=r"(r[0]), "=r"(r[1]), "=r"(r[2]), "=r"(r[3]) : "r"(addr));
}

__device__ __forceinline__ void mma_f16(float* c, const unsigned* a, const unsigned* b) {
    asm volatile(
        "mma.sync.aligned.m16n8k16.row.col.f32.f16.f16.f32 "
        "{%0,%1,%2,%3}, {%4,%5,%6,%7}, {%8,%9}, {%0,%1,%2,%3};\n"
        : "+f"(c[0]), "+f"(c[1]), "+f"(c[2]), "+f"(c[3])
        : "r"(a[0]), "r"(a[1]), "r"(a[2]), "r"(a[3]), "r"(b[0]), "r"(b[1]));
}

// ===========================================================================
// Pre-pass (R13): cvt_x | trans_w | trans_cw, partitioned by blockIdx.x.
// Also resets the gemm1 completion counter for this graph replay.
// ===========================================================================
#define PREP_CVTX   8192
#define PREP_TRW    (PREP_CVTX + 2048)
#define PREP_TOTAL  (PREP_TRW + 4096)

__global__ __launch_bounds__(256)
void prep_kernel(const float* __restrict__ x, const float* __restrict__ W,
                 const float* __restrict__ cw) {
    __shared__ float tile[32][33];
    const int bx = blockIdx.x;
    const int tx = threadIdx.x & 31;
    const int ty = threadIdx.x >> 5;

    if (bx == 0 && threadIdx.x == 0) g_done = 0;   // reset gate (stream-ordered)

    if (bx < PREP_CVTX) {
        long i = ((long)bx * 256 + threadIdx.x) * 8;
        float4 v0 = *(const float4*)(x + i);
        float4 v1 = *(const float4*)(x + i + 4);
        __half2* o = (__half2*)(g_xh + i);
        o[0] = __floats2half2_rn(v0.x, v0.y);
        o[1] = __floats2half2_rn(v0.z, v0.w);
        o[2] = __floats2half2_rn(v1.x, v1.y);
        o[3] = __floats2half2_rn(v1.z, v1.w);
    } else if (bx < PREP_TRW) {
        int t  = bx - PREP_CVTX;
        int g  = t >> 7;
        int rem = t & 127;
        int d0 = (rem >> 4) * 32;
        int f0 = (rem & 15) * 32;
        const float* Wg = W + (long)g * FDIM * DDIM;
#pragma unroll
        for (int j = 0; j < 4; j++) {
            int f = ty + j * 8;
            tile[f][tx] = Wg[(long)(f0 + f) * DDIM + d0 + tx];
        }
        __syncthreads();
        __half* dst = g_wT + (long)g * DDIM * FDIM;
#pragma unroll
        for (int j = 0; j < 4; j++) {
            int d = ty + j * 8;
            dst[(long)(d0 + d) * FDIM + f0 + tx] = __float2half_rn(tile[tx][d]);
        }
    } else {
        int t  = bx - PREP_TRW;
        int o0 = (t >> 8) * 32;
        int k0 = (t & 255) * 32;
#pragma unroll
        for (int j = 0; j < 4; j++) {
            int k = ty + j * 8;
            tile[k][tx] = cw[(long)(k0 + k) * OCH + o0 + tx];
        }
        __syncthreads();
#pragma unroll
        for (int j = 0; j < 4; j++) {
            int o = ty + j * 8;
            g_cwT[(long)(o0 + o) * KTOT + k0 + tx] = __float2half_rn(tile[tx][o]);
        }
    }
}

// ===========================================================================
// FUSED main kernel: one launch, 1280 blocks of 128 threads.
//   bx <  256 : gather + grouped GEMM CTA (R13 config: 128x128 per m-tile,
//               2 m-tiles/CTA, 4 warps 64x64). After epilogue: fence + count.
//   bx >= 256 : conv CTA (R7/R13 config), spins on g_done==256 first.
//               gemm1 blocks have the lowest ids -> scheduled in wave 1 ->
//               no deadlock; conv blocks fill slots as gemm1 CTAs retire.
// ===========================================================================
#define BKH 64
#define A_TILE 16384
#define STAGE_B 32768
#define FUSED_SMEM (3 * STAGE_B + 1024)   // 97.25 KB -> 2 CTAs/SM
#define N_GEMM 256
#define N_TOTAL (N_GEMM + 1024)

__global__ __launch_bounds__(128, 2)
void fused_kernel(const int* __restrict__ idx, const float* __restrict__ bias,
                  const float* __restrict__ cb, float* __restrict__ y) {
    extern __shared__ __align__(128) char smem[];
    unsigned smem_base;
    asm("{ .reg .u64 t; cvta.to.shared.u64 t, %1; cvt.u32.u64 %0, t; }"
        : "=r"(smem_base) : "l"(smem));

    const int bx = blockIdx.x;
    const int tid  = threadIdx.x;
    const int lane = tid & 31;
    const int warp = tid >> 5;
    const int wm = warp >> 1;
    const int wn = warp & 1;
    const int gi = lane >> 2;
    const int tl = lane & 3;
    const int grp8 = lane >> 3;
    const int r8   = lane & 7;

    if (bx < N_GEMM) {
        // ================= GEMM1 CTA =================
        int* rowbase = (int*)(smem + 3 * STAGE_B);

        const int grp   = bx >> 4;
        const int mpair = (bx >> 1) & 7;
        const int n0    = (bx & 1) * 128;

#pragma unroll
        for (int j = 0; j < 2; j++) {
            int m  = mpair * 256 + tid + j * 128;
            int bb = m >> 6;
            int s  = m & 63;
            rowbase[tid + j * 128] = bb * NTOK + idx[grp * SEQ + s];
        }
        __syncthreads();

        const __half* Bsrc = g_wT + (long)grp * DDIM * FDIM;

        float acc[4][8][4];
#pragma unroll
        for (int mt = 0; mt < 4; mt++)
#pragma unroll
            for (int nt = 0; nt < 8; nt++)
#pragma unroll
                for (int i = 0; i < 4; i++) acc[mt][nt][i] = 0.f;

        const int NS = 16;

        auto load_stage = [&](int it) {
            const int mt2 = it >> 3;
            const int ks  = (it & 7) * BKH;
            const int buf = it % 3;
            const unsigned abase = smem_base + buf * STAGE_B;
            const unsigned bbase = abase + A_TILE;
#pragma unroll
            for (int i = 0; i < 8; i++) {
                int c   = tid + i * 128;
                int row = c >> 3;
                int ch  = c & 7;
                cp16(abase + row * 128 + ((ch ^ (row & 7)) * 16),
                     g_xh + (long)rowbase[mt2 * 128 + row] * FDIM + ks + ch * 8, 16);
            }
#pragma unroll
            for (int i = 0; i < 8; i++) {
                int c   = tid + i * 128;
                int row = c >> 3;
                int ch  = c & 7;
                cp16(bbase + row * 128 + ((ch ^ (row & 7)) * 16),
                     Bsrc + (long)(n0 + row) * FDIM + ks + ch * 8, 16);
            }
            asm volatile("cp.async.commit_group;\n");
        };

        auto epilogue = [&](int mt2) {
            const int mbase = mpair * 256 + mt2 * 128;
#pragma unroll
            for (int mt = 0; mt < 4; mt++) {
                int r0 = mbase + wm * 64 + mt * 16 + gi;
                int r1 = r0 + 8;
#pragma unroll
                for (int nt = 0; nt < 8; nt++) {
                    int c = n0 + wn * 64 + nt * 8 + 2 * tl;
                    float2 bv = *(const float2*)(bias + grp * DDIM + c);
                    {
                        int bb = r0 >> 6, s = r0 & 63;
                        __half2* dst = (__half2*)(g_mid + ((long)(bb * NTOK + grp * SEQ + s)) * DDIM + c);
                        *dst = __floats2half2_rn(acc[mt][nt][0] + bv.x, acc[mt][nt][1] + bv.y);
                    }
                    {
                        int bb = r1 >> 6, s = r1 & 63;
                        __half2* dst = (__half2*)(g_mid + ((long)(bb * NTOK + grp * SEQ + s)) * DDIM + c);
                        *dst = __floats2half2_rn(acc[mt][nt][2] + bv.x, acc[mt][nt][3] + bv.y);
                    }
                    acc[mt][nt][0] = 0.f; acc[mt][nt][1] = 0.f;
                    acc[mt][nt][2] = 0.f; acc[mt][nt][3] = 0.f;
                }
            }
        };

        load_stage(0);
        load_stage(1);

#pragma unroll 1
        for (int s = 0; s < NS; s++) {
            if (s + 1 < NS) asm volatile("cp.async.wait_group 1;\n");
            else            asm volatile("cp.async.wait_group 0;\n");
            __syncthreads();

            if (s == 8) epilogue(0);

            if (s + 2 < NS) load_stage(s + 2);

            const int buf = s % 3;
            const unsigned abase = smem_base + buf * STAGE_B;
            const unsigned bbase = abase + A_TILE;

#pragma unroll
            for (int k4 = 0; k4 < 4; k4++) {
                const int kc = k4 * 2;
                unsigned af[4][4];
                unsigned bf[4][4];
#pragma unroll
                for (int mt = 0; mt < 4; mt++) {
                    int row = wm * 64 + mt * 16 + (grp8 & 1) * 8 + r8;
                    int ch  = kc + (grp8 >> 1);
                    ldsm4(af[mt], abase + row * 128 + ((ch ^ (row & 7)) * 16));
                }
#pragma unroll
                for (int q = 0; q < 4; q++) {
                    int row = wn * 64 + q * 16 + (grp8 >> 1) * 8 + r8;
                    int ch  = kc + (grp8 & 1);
                    ldsm4(bf[q], bbase + row * 128 + ((ch ^ (row & 7)) * 16));
                }
#pragma unroll
                for (int mt = 0; mt < 4; mt++)
#pragma unroll
                    for (int nt = 0; nt < 8; nt++)
                        mma_f16(acc[mt][nt], af[mt], &bf[nt >> 1][(nt & 1) * 2]);
            }
        }

        epilogue(1);

        // signal completion (release)
        __syncthreads();
        if (tid == 0) {
            __threadfence();
            atomicAdd(&g_done, 1u);
        }
        return;
    }

    // ================= CONV CTA =================
    {
        const int id2 = bx - N_GEMM;
        const int b   = id2 >> 5;
        const int rem = id2 & 31;
        const int n0  = (rem & 3) * 128;
        const int t0  = (rem >> 2) * 128;

        // gate: wait until all 256 gemm1 CTAs have committed g_mid
        if (tid == 0) {
            unsigned v;
            do {
                asm volatile("ld.acquire.gpu.global.u32 %0, [%1];"
                             : "=r"(v) : "l"(&g_done) : "memory");
                if (v >= N_GEMM) break;
                __nanosleep(256);
            } while (true);
        }
        __syncthreads();

        const __half* midb = g_mid + (long)b * NTOK * DDIM;

        float acc[4][8][4];
#pragma unroll
        for (int mt = 0; mt < 4; mt++)
#pragma unroll
            for (int nt = 0; nt < 8; nt++)
#pragma unroll
                for (int i = 0; i < 4; i++) acc[mt][nt][i] = 0.f;

        const int NS = KTOT / BKH;   // 128

        auto load_stage = [&](int it) {
            const int ks = it * BKH;
            const int w  = ks >> 8;
            const int d0 = ks & 255;
            const int buf = it % 3;
            const unsigned abase = smem_base + buf * STAGE_B;
            const unsigned bbase = abase + A_TILE;
#pragma unroll
            for (int i = 0; i < 8; i++) {
                int c   = tid + i * 128;
                int row = c >> 3;
                int ch  = c & 7;
                int t   = t0 + row + w;
                cp16(abase + row * 128 + ((ch ^ (row & 7)) * 16),
                     midb + (long)t * DDIM + d0 + ch * 8, (t < NTOK) ? 16 : 0);
            }
#pragma unroll
            for (int i = 0; i < 8; i++) {
                int c   = tid + i * 128;
                int row = c >> 3;
                int ch  = c & 7;
                cp16(bbase + row * 128 + ((ch ^ (row & 7)) * 16),
                     g_cwT + (long)(n0 + row) * KTOT + ks + ch * 8, 16);
            }
            asm volatile("cp.async.commit_group;\n");
        };

        auto ldfrag = [&](unsigned af[4][4], unsigned bf[4][4],
                          int kc, unsigned abase, unsigned bbase) {
#pragma unroll
            for (int mt = 0; mt < 4; mt++) {
                int row = wm * 64 + mt * 16 + (grp8 & 1) * 8 + r8;
                int ch  = kc + (grp8 >> 1);
                ldsm4(af[mt], abase + row * 128 + ((ch ^ (row & 7)) * 16));
            }
#pragma unroll
            for (int q = 0; q < 4; q++) {
                int row = wn * 64 + q * 16 + (grp8 >> 1) * 8 + r8;
                int ch  = kc + (grp8 & 1);
                ldsm4(bf[q], bbase + row * 128 + ((ch ^ (row & 7)) * 16));
            }
        };

        load_stage(0);
        load_stage(1);

        unsigned af[2][4][4];
        unsigned bf[2][4][4];

#pragma unroll 1
        for (int s = 0; s < NS; s++) {
            if (s + 1 < NS) asm volatile("cp.async.wait_group 1;\n");
            else            asm volatile("cp.async.wait_group 0;\n");
            __syncthreads();

            if (s + 2 < NS) load_stage(s + 2);

            const int buf = s % 3;
            const unsigned abase = smem_base + buf * STAGE_B;
            const unsigned bbase = abase + A_TILE;

            ldfrag(af[0], bf[0], 0, abase, bbase);

#pragma unroll
            for (int k4 = 0; k4 < 4; k4++) {
                const int cur = k4 & 1;
                if (k4 < 3)
                    ldfrag(af[cur ^ 1], bf[cur ^ 1], (k4 + 1) * 2, abase, bbase);
#pragma unroll
                for (int mt = 0; mt < 4; mt++)
#pragma unroll
                    for (int nt = 0; nt < 8; nt++)
                        mma_f16(acc[mt][nt], af[cur][mt], &bf[cur][nt >> 1][(nt & 1) * 2]);
            }
        }

        // epilogue: bias + leaky relu
#pragma unroll
        for (int mt = 0; mt < 4; mt++) {
            int r0 = t0 + wm * 64 + mt * 16 + gi;
            int r1 = r0 + 8;
#pragma unroll
            for (int nt = 0; nt < 8; nt++) {
                int c = n0 + wn * 64 + nt * 8 + 2 * tl;
                float2 bv = *(const float2*)(cb + c);
                if (r0 < TOUT) {
                    float v0 = acc[mt][nt][0] + bv.x;
                    float v1 = acc[mt][nt][1] + bv.y;
                    v0 = (v0 >= 0.f) ? v0 : NEG_SLOPE * v0;
                    v1 = (v1 >= 0.f) ? v1 : NEG_SLOPE * v1;
                    *(float2*)(y + ((long)b * TOUT + r0) * OCH + c) = make_float2(v0, v1);
                }
                if (r1 < TOUT) {
                    float v2 = acc[mt][nt][2] + bv.x;
                    float v3 = acc[mt][nt][3] + bv.y;
                    v2 = (v2 >= 0.f) ? v2 : NEG_SLOPE * v2;
                    v3 = (v3 >= 0.f) ? v3 : NEG_SLOPE * v3;
                    *(float2*)(y + ((long)b * TOUT + r1) * OCH + c) = make_float2(v2, v3);
                }
            }
        }
    }
}

// ===========================================================================
extern "C" void kernel_launch(void* const* d_in, const int* in_sizes, int n_in,
                              void* d_out, int out_size) {
    const float* x    = (const float*)d_in[0];
    const int*   idx  = (const int*)  d_in[1];
    const float* W    = (const float*)d_in[2];
    const float* bias = (const float*)d_in[3];
    const float* cw   = (const float*)d_in[4];
    const float* cb   = (const float*)d_in[5];
    float* y = (float*)d_out;

    cudaFuncSetAttribute(fused_kernel,
                         cudaFuncAttributeMaxDynamicSharedMemorySize, FUSED_SMEM);

    prep_kernel<<<PREP_TOTAL, 256>>>(x, W, cw);

    fused_kernel<<<N_TOTAL, 128, FUSED_SMEM>>>(idx, bias, cb, y);
}